// round 2
// baseline (speedup 1.0000x reference)
#include <cuda_runtime.h>
#include <math.h>

// Problem constants
#define B_  64
#define T_  512
#define H_  1024
#define I_  1024
#define M_TOK (B_ * T_)          // 32768 rows for the input projection

#define GRID_BLOCKS 128          // persistent kernel grid (must all be co-resident)
#define KSPLIT 16                // K chunks of 64
#define KCHUNK 64
#define NTILE  128               // cols per block tile

// ---------------------------------------------------------------------------
// Scratch (no cudaMalloc allowed -> __device__ globals)
// ---------------------------------------------------------------------------
__device__ float g_xw[M_TOK * H_];              // input-projection result
__device__ float g_y0[M_TOK * H_];              // layer-0 output sequence
__device__ float g_h[B_ * H_];                  // hidden state
__device__ float g_partial[KSPLIT * B_ * H_];   // split-K partials (4 MB)

// grid barrier state
__device__ unsigned g_count = 0;
__device__ volatile unsigned g_gen = 0;

__device__ __forceinline__ void grid_barrier()
{
    __syncthreads();
    if (threadIdx.x == 0) {
        unsigned gen = g_gen;
        __threadfence();                       // make prior stores visible
        unsigned a = atomicAdd(&g_count, 1);
        if (a == GRID_BLOCKS - 1) {
            atomicExch(&g_count, 0);
            __threadfence();
            g_gen = gen + 1;
        } else {
            while (g_gen == gen) { }
        }
    }
    __syncthreads();
}

// ---------------------------------------------------------------------------
// Input-projection GEMM: C[m][n] = sum_k A[m][k] * W[n][k] + b1[n] + b2[n]
// 128x128 tile, BK=16, 256 threads, 8x8 per thread.
// ---------------------------------------------------------------------------
__global__ __launch_bounds__(256) void gemm_bias_kernel(
    const float* __restrict__ A,
    const float* __restrict__ W,
    const float* __restrict__ b1,
    const float* __restrict__ b2,
    float* __restrict__ C,
    int M, int N, int K)
{
    __shared__ float As[16][128];
    __shared__ float Ws[16][128];

    const int m0 = blockIdx.y * 128;
    const int n0 = blockIdx.x * 128;
    const int tid = threadIdx.x;
    const int ty = tid >> 4;
    const int tx = tid & 15;

    const float* Ap = A + (size_t)m0 * K;
    const float* Wp = W + (size_t)n0 * K;

    float acc[8][8];
#pragma unroll
    for (int i = 0; i < 8; i++)
#pragma unroll
        for (int j = 0; j < 8; j++) acc[i][j] = 0.0f;

    for (int k0 = 0; k0 < K; k0 += 16) {
#pragma unroll
        for (int i = 0; i < 2; i++) {
            int f   = tid + i * 256;
            int row = f >> 2;
            int kq  = (f & 3) * 4;
            float4 av = *(const float4*)(Ap + (size_t)row * K + k0 + kq);
            As[kq + 0][row] = av.x;
            As[kq + 1][row] = av.y;
            As[kq + 2][row] = av.z;
            As[kq + 3][row] = av.w;
            float4 wv = *(const float4*)(Wp + (size_t)row * K + k0 + kq);
            Ws[kq + 0][row] = wv.x;
            Ws[kq + 1][row] = wv.y;
            Ws[kq + 2][row] = wv.z;
            Ws[kq + 3][row] = wv.w;
        }
        __syncthreads();

#pragma unroll
        for (int kk = 0; kk < 16; kk++) {
            float a[8], w[8];
            *(float4*)(a)     = *(const float4*)&As[kk][ty * 8];
            *(float4*)(a + 4) = *(const float4*)&As[kk][ty * 8 + 4];
            *(float4*)(w)     = *(const float4*)&Ws[kk][tx * 8];
            *(float4*)(w + 4) = *(const float4*)&Ws[kk][tx * 8 + 4];
#pragma unroll
            for (int i = 0; i < 8; i++)
#pragma unroll
                for (int j = 0; j < 8; j++)
                    acc[i][j] += a[i] * w[j];
        }
        __syncthreads();
    }

    float bv[8];
#pragma unroll
    for (int j = 0; j < 8; j++) {
        int n = n0 + tx * 8 + j;
        bv[j] = b1[n] + b2[n];
    }
#pragma unroll
    for (int i = 0; i < 8; i++) {
        int m = m0 + ty * 8 + i;
        float* cp = C + (size_t)m * N + n0 + tx * 8;
        float4 v0, v1;
        v0.x = acc[i][0] + bv[0];
        v0.y = acc[i][1] + bv[1];
        v0.z = acc[i][2] + bv[2];
        v0.w = acc[i][3] + bv[3];
        v1.x = acc[i][4] + bv[4];
        v1.y = acc[i][5] + bv[5];
        v1.z = acc[i][6] + bv[6];
        v1.w = acc[i][7] + bv[7];
        *(float4*)(cp)     = v0;
        *(float4*)(cp + 4) = v1;
    }
}

// ---------------------------------------------------------------------------
// Persistent recurrence kernel (one launch per layer).
// Grid: 128 blocks = 8 N-tiles (128 cols) x 16 K-chunks (64 k). 256 threads.
// Per step: phase A = split-K GEMM partial[ks] = h @ Whh_chunk^T (smem tiles,
// W chunk resident in smem for the whole layer); barrier; phase B = reduce
// partials + xw + tanh -> h, y; barrier.
// ---------------------------------------------------------------------------
__global__ __launch_bounds__(256) void rnn_layer_persistent(
    const float* __restrict__ Whh,    // [H, H]
    const float* __restrict__ xw,     // [B, T, H]
    float* __restrict__ y,            // [B, T, H]
    float* __restrict__ hlast)        // [B, H]
{
    __shared__ float Ws[KCHUNK][NTILE];   // 32 KB, W[c0+c][k0+k] -> Ws[k][c]
    __shared__ float Hs[KCHUNK][B_];      // 16 KB, h[b][k0+k]   -> Hs[k][b]

    const int tid = threadIdx.x;
    const int nt  = blockIdx.x >> 4;      // 0..7   N tile
    const int ks  = blockIdx.x & 15;      // 0..15  K chunk
    const int c0  = nt * NTILE;
    const int k0  = ks * KCHUNK;

    float* h       = g_h;
    float* partial = g_partial;

    // ---- load W chunk into smem once (persists across all steps) ----
    {
        int c   = tid & 127;
        int kq0 = tid >> 7;               // 0..1
#pragma unroll
        for (int i = 0; i < 8; i++) {
            int kq = kq0 + 2 * i;         // 0..15
            float4 v = *(const float4*)(Whh + (size_t)(c0 + c) * H_ + k0 + kq * 4);
            Ws[kq * 4 + 0][c] = v.x;
            Ws[kq * 4 + 1][c] = v.y;
            Ws[kq * 4 + 2][c] = v.z;
            Ws[kq * 4 + 3][c] = v.w;
        }
    }

    // ---- zero h cooperatively ----
    {
        int g = blockIdx.x * 512 + tid * 2;
        *(float2*)(h + g) = make_float2(0.0f, 0.0f);
    }
    grid_barrier();

    const int tx = tid & 15;              // col group: 8 cols
    const int ty = tid >> 4;              // row group: 4 rows

    for (int t = 0; t < T_; t++) {
        // ---------- phase A: partial[ks][b][c] = sum_k h[b][k]*W[c][k] ----------
        {
            int b   = tid & 63;
            int q0  = tid >> 6;           // 0..3
#pragma unroll
            for (int i = 0; i < 4; i++) {
                int q = q0 + 4 * i;       // 0..15
                float4 v = __ldcg((const float4*)(h + (size_t)b * H_ + k0 + q * 4));
                Hs[q * 4 + 0][b] = v.x;
                Hs[q * 4 + 1][b] = v.y;
                Hs[q * 4 + 2][b] = v.z;
                Hs[q * 4 + 3][b] = v.w;
            }
        }
        __syncthreads();

        float acc[4][8];
#pragma unroll
        for (int i = 0; i < 4; i++)
#pragma unroll
            for (int j = 0; j < 8; j++) acc[i][j] = 0.0f;

#pragma unroll 4
        for (int kk = 0; kk < KCHUNK; kk++) {
            float a[4], w[8];
            *(float4*)(a)     = *(const float4*)&Hs[kk][ty * 4];
            *(float4*)(w)     = *(const float4*)&Ws[kk][tx * 8];
            *(float4*)(w + 4) = *(const float4*)&Ws[kk][tx * 8 + 4];
#pragma unroll
            for (int i = 0; i < 4; i++)
#pragma unroll
                for (int j = 0; j < 8; j++)
                    acc[i][j] += a[i] * w[j];
        }

        // write partial tile
#pragma unroll
        for (int i = 0; i < 4; i++) {
            int m = ty * 4 + i;
            float* pp = partial + (size_t)ks * (B_ * H_) + (size_t)m * H_ + c0 + tx * 8;
            float4 v0 = make_float4(acc[i][0], acc[i][1], acc[i][2], acc[i][3]);
            float4 v1 = make_float4(acc[i][4], acc[i][5], acc[i][6], acc[i][7]);
            *(float4*)(pp)     = v0;
            *(float4*)(pp + 4) = v1;
        }

        grid_barrier();

        // ---------- phase B: reduce + tanh -> h, y ----------
        {
            int idx0 = (blockIdx.x * 256 + tid) * 2;      // 2 outputs/thread
            float sx = 0.0f, sy = 0.0f;
#pragma unroll
            for (int k = 0; k < KSPLIT; k++) {
                float2 p = __ldcg((const float2*)(partial + (size_t)k * (B_ * H_) + idx0));
                sx += p.x;
                sy += p.y;
            }
            int b = idx0 >> 10;
            int c = idx0 & 1023;
            const float* xp = xw + ((size_t)b * T_ + t) * H_ + c;
            float2 xv = *(const float2*)xp;
            float v0 = tanhf(sx + xv.x);
            float v1 = tanhf(sy + xv.y);
            float2 r = make_float2(v0, v1);
            *(float2*)(h + idx0) = r;
            *(float2*)(y + ((size_t)b * T_ + t) * H_ + c) = r;
            if (t == T_ - 1)
                *(float2*)(hlast + idx0) = r;
        }

        grid_barrier();
    }
}

// ---------------------------------------------------------------------------
// Launcher: 4 graph nodes total.
// ---------------------------------------------------------------------------
extern "C" void kernel_launch(void* const* d_in, const int* in_sizes, int n_in,
                              void* d_out, int out_size)
{
    const float* X     = (const float*)d_in[0];
    const float* W_ih0 = (const float*)d_in[1];
    const float* b_ih0 = (const float*)d_in[2];
    const float* W_hh0 = (const float*)d_in[3];
    const float* b_hh0 = (const float*)d_in[4];
    const float* W_ih1 = (const float*)d_in[5];
    const float* b_ih1 = (const float*)d_in[6];
    const float* W_hh1 = (const float*)d_in[7];
    const float* b_hh1 = (const float*)d_in[8];

    float* out    = (float*)d_out;
    float* y_out  = out;                       // [B, T, H]
    float* h_last = out + (size_t)M_TOK * H_;  // [2, B, H]

    float* xw = nullptr;
    float* y0 = nullptr;
    cudaGetSymbolAddress((void**)&xw, g_xw);
    cudaGetSymbolAddress((void**)&y0, g_y0);

    dim3 ggrid(H_ / 128, M_TOK / 128);   // (8, 256)

    // ---------------- layer 0 ----------------
    gemm_bias_kernel<<<ggrid, 256>>>(X, W_ih0, b_ih0, b_hh0, xw, M_TOK, H_, I_);
    rnn_layer_persistent<<<GRID_BLOCKS, 256>>>(W_hh0, xw, y0, h_last);

    // ---------------- layer 1 ----------------
    gemm_bias_kernel<<<ggrid, 256>>>(y0, W_ih1, b_ih1, b_hh1, xw, M_TOK, H_, H_);
    rnn_layer_persistent<<<GRID_BLOCKS, 256>>>(W_hh1, xw, y_out, h_last + B_ * H_);
}